// round 4
// baseline (speedup 1.0000x reference)
#include <cuda_runtime.h>
#include <cstdint>

#define N_NODES  100000
#define N_EDGES  1600000
#define N_GRAPHS 512

// ---------------- scratch (device globals; referenced directly in kernels) --
__device__ int   g_counts[N_NODES];
__device__ int   g_rowstart[N_NODES + 1];
__device__ int   g_pos[N_NODES];
__device__ int   g_esrc[N_EDGES];
__device__ int   g_blocksums[128];
__device__ float g_dinv[N_NODES];
__device__ float g_W1p[80 * 128];
__device__ float g_aggX[(size_t)N_NODES * 80];
__device__ float g_h1[(size_t)N_NODES * 128];
__device__ float g_aggH[(size_t)N_NODES * 128];
__device__ float g_h2[(size_t)N_NODES * 256];
__device__ float g_pool[N_GRAPHS * 256];
__device__ float g_mlp1[N_GRAPHS * 1024];

// ---------------- CSR build --------------------------------------------------
__global__ void zero_counts_kernel() {
    int i = blockIdx.x * blockDim.x + threadIdx.x;
    if (i < N_NODES) g_counts[i] = 0;
}

__global__ void zero_pool_kernel() {
    int i = blockIdx.x * blockDim.x + threadIdx.x;
    if (i < N_GRAPHS * 256) g_pool[i] = 0.0f;
}

// edge_index is int32 (JAX x64 disabled downcasts int64 -> int32): [2, E] row-major
__global__ void hist_kernel(const int* __restrict__ ei) {
    int e = blockIdx.x * blockDim.x + threadIdx.x;
    if (e < N_EDGES) {
        int d = ei[N_EDGES + e];
        if (d >= 0 && d < N_NODES) atomicAdd(&g_counts[d], 1);
    }
}

__device__ __forceinline__ int warp_incl_scan(int x) {
    int lane = threadIdx.x & 31;
#pragma unroll
    for (int o = 1; o < 32; o <<= 1) {
        int y = __shfl_up_sync(0xffffffffu, x, o);
        if (lane >= o) x += y;
    }
    return x;
}

// chunk = 1024 elems per block (256 threads x 4)
__global__ void scan_chunks_kernel() {
    int base = blockIdx.x * 1024;
    int t = threadIdx.x;
    int i0 = base + t * 4;
    int v[4];
#pragma unroll
    for (int j = 0; j < 4; j++) v[j] = (i0 + j < N_NODES) ? g_counts[i0 + j] : 0;
    int s = v[0] + v[1] + v[2] + v[3];
    int incl = warp_incl_scan(s);
    __shared__ int ws[8];
    int lane = t & 31, wid = t >> 5;
    if (lane == 31) ws[wid] = incl;
    __syncthreads();
    if (wid == 0) {
        int w = (lane < 8) ? ws[lane] : 0;
        w = warp_incl_scan(w);
        if (lane < 8) ws[lane] = w;
    }
    __syncthreads();
    int excl = incl - s + (wid ? ws[wid - 1] : 0);
    int run = excl;
#pragma unroll
    for (int j = 0; j < 4; j++) {
        if (i0 + j < N_NODES) g_rowstart[i0 + j] = run;
        run += v[j];
    }
    if (t == 255) g_blocksums[blockIdx.x] = excl + s;
}

// single block, nb <= 128: inclusive scan converted to exclusive, in place
__global__ void scan_tops_kernel(int nb) {
    int t = threadIdx.x;
    int v = (t < nb) ? g_blocksums[t] : 0;
    int incl = warp_incl_scan(v);
    __shared__ int ws[4];
    int lane = t & 31, wid = t >> 5;
    if (lane == 31) ws[wid] = incl;
    __syncthreads();
    if (wid == 0) {
        int w = (lane < 4) ? ws[lane] : 0;
        w = warp_incl_scan(w);
        if (lane < 4) ws[lane] = w;
    }
    __syncthreads();
    int tot_incl = incl + (wid ? ws[wid - 1] : 0);
    if (t < nb) g_blocksums[t] = tot_incl - v;
}

__global__ void scan_finalize_kernel() {
    int i = blockIdx.x * blockDim.x + threadIdx.x;
    if (i < N_NODES) {
        int v = g_rowstart[i] + g_blocksums[i >> 10];
        g_rowstart[i] = v;
        g_pos[i] = v;
        g_dinv[i] = rsqrtf((float)g_counts[i] + 1.0f);
    }
    if (i == 0) g_rowstart[N_NODES] = N_EDGES;
}

__global__ void fill_kernel(const int* __restrict__ ei) {
    int e = blockIdx.x * blockDim.x + threadIdx.x;
    if (e < N_EDGES) {
        int d = ei[N_EDGES + e];
        int s = ei[e];
        if (d >= 0 && d < N_NODES) {
            int idx = atomicAdd(&g_pos[d], 1);
            if (idx >= 0 && idx < N_EDGES) g_esrc[idx] = s;
        }
    }
}

__global__ void pad_w1_kernel(const float* __restrict__ W1) {
    int i = blockIdx.x * blockDim.x + threadIdx.x;  // 80*128
    if (i < 80 * 128) {
        int r = i / 128, c = i % 128;
        g_W1p[i] = (r < 78) ? W1[r * 128 + c] : 0.0f;
    }
}

// ---------------- aggregation (warp per destination node) -------------------
// aggX[i,0:78] = sum_{e:dst=i} x[src]*dinv[src]*dinv[i] + x[i]*dinv[i]^2 ; cols 78,79 = 0
__global__ void agg_x_kernel(const float* __restrict__ x) {
    int warp = (blockIdx.x * blockDim.x + threadIdx.x) >> 5;
    int lane = threadIdx.x & 31;
    if (warp >= N_NODES) return;
    int i = warp;
    float di = g_dinv[i];
    int beg = g_rowstart[i], end = g_rowstart[i + 1];
    float a0 = 0.f, a1 = 0.f, a2 = 0.f;
    for (int e = beg; e < end; e++) {
        int s = g_esrc[e];
        float w = g_dinv[s] * di;
        const float* xs = x + (size_t)s * 78;
        a0 += xs[lane] * w;
        a1 += xs[lane + 32] * w;
        if (lane < 14) a2 += xs[lane + 64] * w;
    }
    float sd = di * di;
    const float* xi = x + (size_t)i * 78;
    a0 += xi[lane] * sd;
    a1 += xi[lane + 32] * sd;
    if (lane < 14) a2 += xi[lane + 64] * sd;
    float* o = g_aggX + (size_t)i * 80;
    o[lane] = a0;
    o[lane + 32] = a1;
    if (lane < 16) o[lane + 64] = (lane < 14) ? a2 : 0.0f;
}

// aggH[i,:] over h1 [N,128], float4 per lane (32 lanes x 4 floats = 128)
__global__ void agg_h_kernel() {
    int warp = (blockIdx.x * blockDim.x + threadIdx.x) >> 5;
    int lane = threadIdx.x & 31;
    if (warp >= N_NODES) return;
    int i = warp;
    float di = g_dinv[i];
    int beg = g_rowstart[i], end = g_rowstart[i + 1];
    float4 acc = make_float4(0.f, 0.f, 0.f, 0.f);
    for (int e = beg; e < end; e++) {
        int s = g_esrc[e];
        float w = g_dinv[s] * di;
        float4 v = ((const float4*)(g_h1 + (size_t)s * 128))[lane];
        acc.x += v.x * w; acc.y += v.y * w; acc.z += v.z * w; acc.w += v.w * w;
    }
    float sd = di * di;
    float4 v = ((const float4*)(g_h1 + (size_t)i * 128))[lane];
    acc.x += v.x * sd; acc.y += v.y * sd; acc.z += v.z * sd; acc.w += v.w * sd;
    ((float4*)(g_aggH + (size_t)i * 128))[lane] = acc;
}

// ---------------- segment max over sorted batch ------------------------------
// block = 128 nodes, 256 threads = features; running max, flush on graph change
// h2 >= 0 (post-ReLU), so int-compare atomicMax on float bits is order-correct
// and 0-initialized pool is the identity. batch is int32 (JAX x64 off).
__global__ void seg_max_kernel(const int* __restrict__ batch) {
    int f = threadIdx.x;  // 0..255
    int n0 = blockIdx.x * 128;
    if (n0 >= N_NODES) return;
    int n1 = min(n0 + 128, N_NODES);
    int cur = batch[n0];
    float m = g_h2[(size_t)n0 * 256 + f];
    for (int n = n0 + 1; n < n1; n++) {
        int b = batch[n];
        float v = g_h2[(size_t)n * 256 + f];
        if (b != cur) {
            if (cur >= 0 && cur < N_GRAPHS)
                atomicMax((int*)&g_pool[(size_t)cur * 256 + f], __float_as_int(m));
            cur = b;
            m = v;
        } else {
            m = fmaxf(m, v);
        }
    }
    if (cur >= 0 && cur < N_GRAPHS)
        atomicMax((int*)&g_pool[(size_t)cur * 256 + f], __float_as_int(m));
}

// ---------------- dedicated micro-tiled SGEMMs (bias + optional relu) -------

__global__ void __launch_bounds__(256)
sgemm1_kernel(const float* __restrict__ bias) {  // aggX(80) @ W1p -> h1 [N,128] relu
    constexpr int BM = 64, BN = 128, KC = 16, TM = 8, TN = 4, NT = 256;
    __shared__ __align__(16) float As[KC][BM];
    __shared__ __align__(16) float Bs[KC][BN];
    const float* A = g_aggX; const float* B = g_W1p; float* C = g_h1;
    const int lda = 80, ldb = 128, ldc = 128, nrows = N_NODES, K = 80;
    int tid = threadIdx.x;
    int tx = tid % (BN / TN), ty = tid / (BN / TN);
    int rowBase = blockIdx.y * BM, colBase = blockIdx.x * BN;
    float acc[TM][TN];
#pragma unroll
    for (int i = 0; i < TM; i++)
#pragma unroll
        for (int j = 0; j < TN; j++) acc[i][j] = 0.0f;
    for (int kc = 0; kc < K; kc += KC) {
#pragma unroll
        for (int e = tid * 4; e < BM * KC; e += NT * 4) {
            int r = e / KC, k = e % KC;
            int row = rowBase + r;
            float4 v = (row < nrows) ? *(const float4*)&A[(size_t)row * lda + kc + k]
                                     : make_float4(0.f, 0.f, 0.f, 0.f);
            As[k][r] = v.x; As[k + 1][r] = v.y; As[k + 2][r] = v.z; As[k + 3][r] = v.w;
        }
#pragma unroll
        for (int e = tid * 4; e < KC * BN; e += NT * 4) {
            int k = e / BN, c = e % BN;
            *(float4*)&Bs[k][c] = *(const float4*)&B[(size_t)(kc + k) * ldb + colBase + c];
        }
        __syncthreads();
#pragma unroll
        for (int k = 0; k < KC; k++) {
            float a[TM], b[TN];
#pragma unroll
            for (int i = 0; i < TM; i++) a[i] = As[k][ty * TM + i];
#pragma unroll
            for (int j = 0; j < TN; j++) b[j] = Bs[k][tx * TN + j];
#pragma unroll
            for (int i = 0; i < TM; i++)
#pragma unroll
                for (int j = 0; j < TN; j++) acc[i][j] += a[i] * b[j];
        }
        __syncthreads();
    }
#pragma unroll
    for (int i = 0; i < TM; i++) {
        int row = rowBase + ty * TM + i;
        if (row >= nrows) continue;
#pragma unroll
        for (int j = 0; j < TN; j++) {
            int col = colBase + tx * TN + j;
            C[(size_t)row * ldc + col] = fmaxf(acc[i][j] + bias[col], 0.0f);
        }
    }
}

__global__ void __launch_bounds__(256)
sgemm2_kernel(const float* __restrict__ W2, const float* __restrict__ bias) {
    // aggH(128) @ W2 -> h2 [N,256] relu
    constexpr int BM = 64, BN = 128, KC = 16, TM = 8, TN = 4, NT = 256;
    __shared__ __align__(16) float As[KC][BM];
    __shared__ __align__(16) float Bs[KC][BN];
    const float* A = g_aggH; const float* B = W2; float* C = g_h2;
    const int lda = 128, ldb = 256, ldc = 256, nrows = N_NODES, K = 128;
    int tid = threadIdx.x;
    int tx = tid % (BN / TN), ty = tid / (BN / TN);
    int rowBase = blockIdx.y * BM, colBase = blockIdx.x * BN;
    float acc[TM][TN];
#pragma unroll
    for (int i = 0; i < TM; i++)
#pragma unroll
        for (int j = 0; j < TN; j++) acc[i][j] = 0.0f;
    for (int kc = 0; kc < K; kc += KC) {
#pragma unroll
        for (int e = tid * 4; e < BM * KC; e += NT * 4) {
            int r = e / KC, k = e % KC;
            int row = rowBase + r;
            float4 v = (row < nrows) ? *(const float4*)&A[(size_t)row * lda + kc + k]
                                     : make_float4(0.f, 0.f, 0.f, 0.f);
            As[k][r] = v.x; As[k + 1][r] = v.y; As[k + 2][r] = v.z; As[k + 3][r] = v.w;
        }
#pragma unroll
        for (int e = tid * 4; e < KC * BN; e += NT * 4) {
            int k = e / BN, c = e % BN;
            *(float4*)&Bs[k][c] = *(const float4*)&B[(size_t)(kc + k) * ldb + colBase + c];
        }
        __syncthreads();
#pragma unroll
        for (int k = 0; k < KC; k++) {
            float a[TM], b[TN];
#pragma unroll
            for (int i = 0; i < TM; i++) a[i] = As[k][ty * TM + i];
#pragma unroll
            for (int j = 0; j < TN; j++) b[j] = Bs[k][tx * TN + j];
#pragma unroll
            for (int i = 0; i < TM; i++)
#pragma unroll
                for (int j = 0; j < TN; j++) acc[i][j] += a[i] * b[j];
        }
        __syncthreads();
    }
#pragma unroll
    for (int i = 0; i < TM; i++) {
        int row = rowBase + ty * TM + i;
        if (row >= nrows) continue;
#pragma unroll
        for (int j = 0; j < TN; j++) {
            int col = colBase + tx * TN + j;
            C[(size_t)row * ldc + col] = fmaxf(acc[i][j] + bias[col], 0.0f);
        }
    }
}

__global__ void __launch_bounds__(256)
mlp1_kernel(const float* __restrict__ Wg1, const float* __restrict__ bias) {
    // pool(256) @ Wg1 -> mlp1 [512,1024] relu
    constexpr int BM = 64, BN = 128, KC = 16, TM = 8, TN = 4, NT = 256;
    __shared__ __align__(16) float As[KC][BM];
    __shared__ __align__(16) float Bs[KC][BN];
    const float* A = g_pool; const float* B = Wg1; float* C = g_mlp1;
    const int lda = 256, ldb = 1024, ldc = 1024, nrows = N_GRAPHS, K = 256;
    int tid = threadIdx.x;
    int tx = tid % (BN / TN), ty = tid / (BN / TN);
    int rowBase = blockIdx.y * BM, colBase = blockIdx.x * BN;
    float acc[TM][TN];
#pragma unroll
    for (int i = 0; i < TM; i++)
#pragma unroll
        for (int j = 0; j < TN; j++) acc[i][j] = 0.0f;
    for (int kc = 0; kc < K; kc += KC) {
#pragma unroll
        for (int e = tid * 4; e < BM * KC; e += NT * 4) {
            int r = e / KC, k = e % KC;
            int row = rowBase + r;
            float4 v = (row < nrows) ? *(const float4*)&A[(size_t)row * lda + kc + k]
                                     : make_float4(0.f, 0.f, 0.f, 0.f);
            As[k][r] = v.x; As[k + 1][r] = v.y; As[k + 2][r] = v.z; As[k + 3][r] = v.w;
        }
#pragma unroll
        for (int e = tid * 4; e < KC * BN; e += NT * 4) {
            int k = e / BN, c = e % BN;
            *(float4*)&Bs[k][c] = *(const float4*)&B[(size_t)(kc + k) * ldb + colBase + c];
        }
        __syncthreads();
#pragma unroll
        for (int k = 0; k < KC; k++) {
            float a[TM], b[TN];
#pragma unroll
            for (int i = 0; i < TM; i++) a[i] = As[k][ty * TM + i];
#pragma unroll
            for (int j = 0; j < TN; j++) b[j] = Bs[k][tx * TN + j];
#pragma unroll
            for (int i = 0; i < TM; i++)
#pragma unroll
                for (int j = 0; j < TN; j++) acc[i][j] += a[i] * b[j];
        }
        __syncthreads();
    }
#pragma unroll
    for (int i = 0; i < TM; i++) {
        int row = rowBase + ty * TM + i;
        if (row >= nrows) continue;
#pragma unroll
        for (int j = 0; j < TN; j++) {
            int col = colBase + tx * TN + j;
            C[(size_t)row * ldc + col] = fmaxf(acc[i][j] + bias[col], 0.0f);
        }
    }
}

__global__ void __launch_bounds__(256)
mlp2_kernel(const float* __restrict__ Wg2, const float* __restrict__ bias,
            float* __restrict__ out) {
    // mlp1(1024) @ Wg2 -> out [512,128], no relu
    constexpr int BM = 8, BN = 128, KC = 16, TM = 1, TN = 4, NT = 256;
    __shared__ __align__(16) float As[KC][BM];
    __shared__ __align__(16) float Bs[KC][BN];
    const float* A = g_mlp1; const float* B = Wg2; float* C = out;
    const int lda = 1024, ldb = 128, ldc = 128, nrows = N_GRAPHS, K = 1024;
    int tid = threadIdx.x;
    int tx = tid % (BN / TN), ty = tid / (BN / TN);
    int rowBase = blockIdx.y * BM, colBase = blockIdx.x * BN;
    float acc[TM][TN];
#pragma unroll
    for (int i = 0; i < TM; i++)
#pragma unroll
        for (int j = 0; j < TN; j++) acc[i][j] = 0.0f;
    for (int kc = 0; kc < K; kc += KC) {
        for (int e = tid; e < BM * KC; e += NT) {
            int r = e / KC, k = e % KC;
            int row = rowBase + r;
            As[k][r] = (row < nrows) ? A[(size_t)row * lda + kc + k] : 0.0f;
        }
#pragma unroll
        for (int e = tid * 4; e < KC * BN; e += NT * 4) {
            int k = e / BN, c = e % BN;
            *(float4*)&Bs[k][c] = *(const float4*)&B[(size_t)(kc + k) * ldb + colBase + c];
        }
        __syncthreads();
#pragma unroll
        for (int k = 0; k < KC; k++) {
            float a[TM], b[TN];
#pragma unroll
            for (int i = 0; i < TM; i++) a[i] = As[k][ty * TM + i];
#pragma unroll
            for (int j = 0; j < TN; j++) b[j] = Bs[k][tx * TN + j];
#pragma unroll
            for (int i = 0; i < TM; i++)
#pragma unroll
                for (int j = 0; j < TN; j++) acc[i][j] += a[i] * b[j];
        }
        __syncthreads();
    }
#pragma unroll
    for (int i = 0; i < TM; i++) {
        int row = rowBase + ty * TM + i;
        if (row >= nrows) continue;
#pragma unroll
        for (int j = 0; j < TN; j++) {
            int col = colBase + tx * TN + j;
            C[(size_t)row * ldc + col] = acc[i][j] + bias[col];
        }
    }
}

// ---------------- host ------------------------------------------------------
extern "C" void kernel_launch(void* const* d_in, const int* in_sizes, int n_in,
                              void* d_out, int out_size) {
    const float* x     = (const float*)d_in[0];
    const int*   ei    = (const int*)d_in[1];    // int32: JAX x64 disabled
    const int*   batch = (const int*)d_in[2];    // int32: JAX x64 disabled
    const float* W1    = (const float*)d_in[3];
    const float* b1    = (const float*)d_in[4];
    const float* W2    = (const float*)d_in[5];
    const float* b2    = (const float*)d_in[6];
    const float* Wg1   = (const float*)d_in[7];
    const float* bg1   = (const float*)d_in[8];
    const float* Wg2   = (const float*)d_in[9];
    const float* bg2   = (const float*)d_in[10];
    float*       out   = (float*)d_out;

    const int NB_SCAN = (N_NODES + 1023) / 1024;  // 98

    // degree histogram + CSR build
    zero_counts_kernel<<<(N_NODES + 255) / 256, 256>>>();
    hist_kernel<<<(N_EDGES + 255) / 256, 256>>>(ei);
    scan_chunks_kernel<<<NB_SCAN, 256>>>();
    scan_tops_kernel<<<1, 128>>>(NB_SCAN);
    scan_finalize_kernel<<<(N_NODES + 255) / 256, 256>>>();
    fill_kernel<<<(N_EDGES + 255) / 256, 256>>>(ei);
    pad_w1_kernel<<<(80 * 128 + 255) / 256, 256>>>(W1);

    // layer 1: aggregate x (78 feats -> 80 padded), then GEMM + bias + relu
    agg_x_kernel<<<N_NODES / 8, 256>>>(x);
    sgemm1_kernel<<<dim3(1, (N_NODES + 63) / 64), 256>>>(b1);

    // layer 2: aggregate h1 (128 feats), then GEMM + bias + relu
    agg_h_kernel<<<N_NODES / 8, 256>>>();
    sgemm2_kernel<<<dim3(2, (N_NODES + 63) / 64), 256>>>(W2, b2);

    // global max pool over sorted batch
    zero_pool_kernel<<<(N_GRAPHS * 256 + 255) / 256, 256>>>();
    seg_max_kernel<<<(N_NODES + 127) / 128, 256>>>(batch);

    // MLP head
    mlp1_kernel<<<dim3(8, 8), 256>>>(Wg1, bg1);
    mlp2_kernel<<<dim3(1, 64), 256>>>(Wg2, bg2, out);
}

// round 5
// speedup vs baseline: 1.1053x; 1.1053x over previous
#include <cuda_runtime.h>
#include <cstdint>

#define N_NODES  100000
#define N_EDGES  1600000
#define N_GRAPHS 512

// ---------------- scratch (device globals; referenced directly in kernels) --
__device__ int   g_counts[N_NODES];
__device__ int   g_rowstart[N_NODES + 1];
__device__ int   g_pos[N_NODES];
__device__ int   g_esrc[N_EDGES];
__device__ int   g_blocksums[128];
__device__ float g_dinv[N_NODES];
__device__ float g_W1p[80 * 128];
__device__ float g_aggX[(size_t)N_NODES * 80];
__device__ float g_h1[(size_t)N_NODES * 128];
__device__ float g_aggH[(size_t)N_NODES * 128];
__device__ float g_h2[(size_t)N_NODES * 256];
__device__ float g_pool[N_GRAPHS * 256];
__device__ float g_mlp1[N_GRAPHS * 1024];

// ---------------- CSR build --------------------------------------------------
__global__ void zero_counts_kernel() {
    int i = blockIdx.x * blockDim.x + threadIdx.x;
    if (i < N_NODES) g_counts[i] = 0;
}

__global__ void zero_pool_kernel() {
    int i = blockIdx.x * blockDim.x + threadIdx.x;
    if (i < N_GRAPHS * 256) g_pool[i] = 0.0f;
}

// edge_index is int32 (JAX x64 disabled downcasts int64 -> int32): [2, E] row-major
__global__ void hist_kernel(const int* __restrict__ ei) {
    int e = blockIdx.x * blockDim.x + threadIdx.x;
    if (e < N_EDGES) {
        int d = ei[N_EDGES + e];
        if (d >= 0 && d < N_NODES) atomicAdd(&g_counts[d], 1);
    }
}

__device__ __forceinline__ int warp_incl_scan(int x) {
    int lane = threadIdx.x & 31;
#pragma unroll
    for (int o = 1; o < 32; o <<= 1) {
        int y = __shfl_up_sync(0xffffffffu, x, o);
        if (lane >= o) x += y;
    }
    return x;
}

// chunk = 1024 elems per block (256 threads x 4)
__global__ void scan_chunks_kernel() {
    int base = blockIdx.x * 1024;
    int t = threadIdx.x;
    int i0 = base + t * 4;
    int v[4];
#pragma unroll
    for (int j = 0; j < 4; j++) v[j] = (i0 + j < N_NODES) ? g_counts[i0 + j] : 0;
    int s = v[0] + v[1] + v[2] + v[3];
    int incl = warp_incl_scan(s);
    __shared__ int ws[8];
    int lane = t & 31, wid = t >> 5;
    if (lane == 31) ws[wid] = incl;
    __syncthreads();
    if (wid == 0) {
        int w = (lane < 8) ? ws[lane] : 0;
        w = warp_incl_scan(w);
        if (lane < 8) ws[lane] = w;
    }
    __syncthreads();
    int excl = incl - s + (wid ? ws[wid - 1] : 0);
    int run = excl;
#pragma unroll
    for (int j = 0; j < 4; j++) {
        if (i0 + j < N_NODES) g_rowstart[i0 + j] = run;
        run += v[j];
    }
    if (t == 255) g_blocksums[blockIdx.x] = excl + s;
}

// single block, nb <= 128: inclusive scan converted to exclusive, in place
__global__ void scan_tops_kernel(int nb) {
    int t = threadIdx.x;
    int v = (t < nb) ? g_blocksums[t] : 0;
    int incl = warp_incl_scan(v);
    __shared__ int ws[4];
    int lane = t & 31, wid = t >> 5;
    if (lane == 31) ws[wid] = incl;
    __syncthreads();
    if (wid == 0) {
        int w = (lane < 4) ? ws[lane] : 0;
        w = warp_incl_scan(w);
        if (lane < 4) ws[lane] = w;
    }
    __syncthreads();
    int tot_incl = incl + (wid ? ws[wid - 1] : 0);
    if (t < nb) g_blocksums[t] = tot_incl - v;
}

__global__ void scan_finalize_kernel() {
    int i = blockIdx.x * blockDim.x + threadIdx.x;
    if (i < N_NODES) {
        int v = g_rowstart[i] + g_blocksums[i >> 10];
        g_rowstart[i] = v;
        g_pos[i] = v;
        g_dinv[i] = rsqrtf((float)g_counts[i] + 1.0f);
    }
    if (i == 0) g_rowstart[N_NODES] = N_EDGES;
}

__global__ void fill_kernel(const int* __restrict__ ei) {
    int e = blockIdx.x * blockDim.x + threadIdx.x;
    if (e < N_EDGES) {
        int d = ei[N_EDGES + e];
        int s = ei[e];
        if (d >= 0 && d < N_NODES) {
            int idx = atomicAdd(&g_pos[d], 1);
            if (idx >= 0 && idx < N_EDGES) g_esrc[idx] = s;
        }
    }
}

__global__ void pad_w1_kernel(const float* __restrict__ W1) {
    int i = blockIdx.x * blockDim.x + threadIdx.x;  // 80*128
    if (i < 80 * 128) {
        int r = i / 128, c = i % 128;
        g_W1p[i] = (r < 78) ? W1[r * 128 + c] : 0.0f;
    }
}

// ---------------- aggregation (warp per destination node) -------------------
__global__ void agg_x_kernel(const float* __restrict__ x) {
    int warp = (blockIdx.x * blockDim.x + threadIdx.x) >> 5;
    int lane = threadIdx.x & 31;
    if (warp >= N_NODES) return;
    int i = warp;
    float di = g_dinv[i];
    int beg = g_rowstart[i], end = g_rowstart[i + 1];
    float a0 = 0.f, a1 = 0.f, a2 = 0.f;
    for (int e = beg; e < end; e++) {
        int s = g_esrc[e];
        float w = g_dinv[s] * di;
        const float* xs = x + (size_t)s * 78;
        a0 += xs[lane] * w;
        a1 += xs[lane + 32] * w;
        if (lane < 14) a2 += xs[lane + 64] * w;
    }
    float sd = di * di;
    const float* xi = x + (size_t)i * 78;
    a0 += xi[lane] * sd;
    a1 += xi[lane + 32] * sd;
    if (lane < 14) a2 += xi[lane + 64] * sd;
    float* o = g_aggX + (size_t)i * 80;
    o[lane] = a0;
    o[lane + 32] = a1;
    if (lane < 16) o[lane + 64] = (lane < 14) ? a2 : 0.0f;
}

__global__ void agg_h_kernel() {
    int warp = (blockIdx.x * blockDim.x + threadIdx.x) >> 5;
    int lane = threadIdx.x & 31;
    if (warp >= N_NODES) return;
    int i = warp;
    float di = g_dinv[i];
    int beg = g_rowstart[i], end = g_rowstart[i + 1];
    float4 acc = make_float4(0.f, 0.f, 0.f, 0.f);
    for (int e = beg; e < end; e++) {
        int s = g_esrc[e];
        float w = g_dinv[s] * di;
        float4 v = ((const float4*)(g_h1 + (size_t)s * 128))[lane];
        acc.x += v.x * w; acc.y += v.y * w; acc.z += v.z * w; acc.w += v.w * w;
    }
    float sd = di * di;
    float4 v = ((const float4*)(g_h1 + (size_t)i * 128))[lane];
    acc.x += v.x * sd; acc.y += v.y * sd; acc.z += v.z * sd; acc.w += v.w * sd;
    ((float4*)(g_aggH + (size_t)i * 128))[lane] = acc;
}

// ---------------- segment max over sorted batch ------------------------------
__global__ void seg_max_kernel(const int* __restrict__ batch) {
    int f = threadIdx.x;  // 0..255
    int n0 = blockIdx.x * 128;
    if (n0 >= N_NODES) return;
    int n1 = min(n0 + 128, N_NODES);
    int cur = batch[n0];
    float m = g_h2[(size_t)n0 * 256 + f];
    for (int n = n0 + 1; n < n1; n++) {
        int b = batch[n];
        float v = g_h2[(size_t)n * 256 + f];
        if (b != cur) {
            if (cur >= 0 && cur < N_GRAPHS)
                atomicMax((int*)&g_pool[(size_t)cur * 256 + f], __float_as_int(m));
            cur = b;
            m = v;
        } else {
            m = fmaxf(m, v);
        }
    }
    if (cur >= 0 && cur < N_GRAPHS)
        atomicMax((int*)&g_pool[(size_t)cur * 256 + f], __float_as_int(m));
}

// ---------------- TF32 tensor-core GEMM (mma.sync m16n8k8) ------------------
// C[nrows, *] = A[nrows, KDIM] @ B[KDIM, LDB cols] + bias, optional ReLU.
// Block tile 128x128, 8 warps: warpRow = wid&3 (32 rows), warpCol = wid>>2 (64 cols).
// Smem pad: PADK % 4 == 0 and PADK*row mod 32 cycles multiples of 4 -> fragment
// LDS (bank = row*4+k pattern) is conflict-free for both A and B tiles.

__device__ __forceinline__ uint32_t f2tf32(float f) {
    uint32_t u;
    asm("cvt.rna.tf32.f32 %0, %1;" : "=r"(u) : "f"(f));
    return u;
}

__device__ __forceinline__ void mma_tf32(float* c, const uint32_t* a,
                                         uint32_t b0, uint32_t b1) {
    asm volatile(
        "mma.sync.aligned.m16n8k8.row.col.f32.tf32.tf32.f32 "
        "{%0,%1,%2,%3}, {%4,%5,%6,%7}, {%8,%9}, {%0,%1,%2,%3};"
        : "+f"(c[0]), "+f"(c[1]), "+f"(c[2]), "+f"(c[3])
        : "r"(a[0]), "r"(a[1]), "r"(a[2]), "r"(a[3]), "r"(b0), "r"(b1));
}

template <int KDIM, int KC, int PADK, int LDA, int LDB, int LDC, bool RELU>
__device__ __forceinline__ void tf32_gemm_body(
    const float* __restrict__ A, const float* __restrict__ B,
    const float* __restrict__ bias, float* __restrict__ C, int nrows) {
    __shared__ uint32_t As[128 * PADK];
    __shared__ uint32_t Bs[128 * PADK];

    int tid = threadIdx.x;
    int wid = tid >> 5, lane = tid & 31;
    int lq = lane >> 2, lr = lane & 3;
    int warpRow = wid & 3, warpCol = wid >> 2;
    int rowBase = blockIdx.y * 128;
    int colBase = blockIdx.x * 128;

    float c[2][8][4];
#pragma unroll
    for (int am = 0; am < 2; am++)
#pragma unroll
        for (int an = 0; an < 8; an++)
#pragma unroll
            for (int j = 0; j < 4; j++) c[am][an][j] = 0.0f;

    for (int kc = 0; kc < KDIM; kc += KC) {
        // A tile: As[row][k] = tf32(A[rowBase+row][kc+k]), zero beyond nrows
#pragma unroll
        for (int i = 0; i < KC / 8; i++) {
            int e = (tid + i * 256) * 4;          // element in 128*KC
            int row = e / KC, k = e % KC;
            int grow = rowBase + row;
            float4 v = (grow < nrows)
                           ? *(const float4*)&A[(size_t)grow * LDA + kc + k]
                           : make_float4(0.f, 0.f, 0.f, 0.f);
            uint32_t* dst = &As[row * PADK + k];
            dst[0] = f2tf32(v.x); dst[1] = f2tf32(v.y);
            dst[2] = f2tf32(v.z); dst[3] = f2tf32(v.w);
        }
        // B tile (transposed): Bs[n][k] = tf32(B[kc+k][colBase+n])
#pragma unroll
        for (int i = 0; i < KC / 8; i++) {
            int e = (tid + i * 256) * 4;          // element in KC*128
            int k = e / 128, n = e % 128;
            float4 v = *(const float4*)&B[(size_t)(kc + k) * LDB + colBase + n];
            Bs[(n + 0) * PADK + k] = f2tf32(v.x);
            Bs[(n + 1) * PADK + k] = f2tf32(v.y);
            Bs[(n + 2) * PADK + k] = f2tf32(v.z);
            Bs[(n + 3) * PADK + k] = f2tf32(v.w);
        }
        __syncthreads();

#pragma unroll
        for (int ks = 0; ks < KC / 8; ks++) {
            uint32_t a[2][4];
#pragma unroll
            for (int am = 0; am < 2; am++) {
                int r = warpRow * 32 + am * 16 + lq;
                a[am][0] = As[r * PADK + ks * 8 + lr];
                a[am][1] = As[(r + 8) * PADK + ks * 8 + lr];
                a[am][2] = As[r * PADK + ks * 8 + lr + 4];
                a[am][3] = As[(r + 8) * PADK + ks * 8 + lr + 4];
            }
#pragma unroll
            for (int an = 0; an < 8; an++) {
                int n = warpCol * 64 + an * 8 + lq;
                uint32_t b0 = Bs[n * PADK + ks * 8 + lr];
                uint32_t b1 = Bs[n * PADK + ks * 8 + lr + 4];
                mma_tf32(c[0][an], a[0], b0, b1);
                mma_tf32(c[1][an], a[1], b0, b1);
            }
        }
        __syncthreads();
    }

    // epilogue: bias (+relu), float2 stores (c0,c1 are adjacent columns)
#pragma unroll
    for (int am = 0; am < 2; am++) {
        int r0 = rowBase + warpRow * 32 + am * 16 + lq;
#pragma unroll
        for (int an = 0; an < 8; an++) {
            int col = colBase + warpCol * 64 + an * 8 + lr * 2;
            float bx = bias[col], by = bias[col + 1];
            float v0 = c[am][an][0] + bx, v1 = c[am][an][1] + by;
            float v2 = c[am][an][2] + bx, v3 = c[am][an][3] + by;
            if (RELU) {
                v0 = fmaxf(v0, 0.f); v1 = fmaxf(v1, 0.f);
                v2 = fmaxf(v2, 0.f); v3 = fmaxf(v3, 0.f);
            }
            if (r0 < nrows) {
                float2 p = make_float2(v0, v1);
                *(float2*)&C[(size_t)r0 * LDC + col] = p;
            }
            if (r0 + 8 < nrows) {
                float2 p = make_float2(v2, v3);
                *(float2*)&C[(size_t)(r0 + 8) * LDC + col] = p;
            }
        }
    }
}

__global__ void __launch_bounds__(256)
gemm1_tf32_kernel(const float* __restrict__ bias) {
    // aggX [N,80] @ W1p [80,128] -> h1 [N,128], relu
    tf32_gemm_body<80, 16, 20, 80, 128, 128, true>(g_aggX, g_W1p, bias, g_h1, N_NODES);
}

__global__ void __launch_bounds__(256)
gemm2_tf32_kernel(const float* __restrict__ W2, const float* __restrict__ bias) {
    // aggH [N,128] @ W2 [128,256] -> h2 [N,256], relu
    tf32_gemm_body<128, 32, 36, 128, 256, 256, true>(g_aggH, W2, bias, g_h2, N_NODES);
}

// ---------------- fp32 MLP head (small) -------------------------------------
__global__ void __launch_bounds__(256)
mlp1_kernel(const float* __restrict__ Wg1, const float* __restrict__ bias) {
    // pool(256) @ Wg1 -> mlp1 [512,1024] relu
    constexpr int BM = 64, BN = 128, KC = 16, TM = 8, TN = 4, NT = 256;
    __shared__ __align__(16) float As[KC][BM];
    __shared__ __align__(16) float Bs[KC][BN];
    const float* A = g_pool; const float* B = Wg1; float* C = g_mlp1;
    const int lda = 256, ldb = 1024, ldc = 1024, nrows = N_GRAPHS, K = 256;
    int tid = threadIdx.x;
    int tx = tid % (BN / TN), ty = tid / (BN / TN);
    int rowBase = blockIdx.y * BM, colBase = blockIdx.x * BN;
    float acc[TM][TN];
#pragma unroll
    for (int i = 0; i < TM; i++)
#pragma unroll
        for (int j = 0; j < TN; j++) acc[i][j] = 0.0f;
    for (int kc = 0; kc < K; kc += KC) {
#pragma unroll
        for (int e = tid * 4; e < BM * KC; e += NT * 4) {
            int r = e / KC, k = e % KC;
            int row = rowBase + r;
            float4 v = (row < nrows) ? *(const float4*)&A[(size_t)row * lda + kc + k]
                                     : make_float4(0.f, 0.f, 0.f, 0.f);
            As[k][r] = v.x; As[k + 1][r] = v.y; As[k + 2][r] = v.z; As[k + 3][r] = v.w;
        }
#pragma unroll
        for (int e = tid * 4; e < KC * BN; e += NT * 4) {
            int k = e / BN, c = e % BN;
            *(float4*)&Bs[k][c] = *(const float4*)&B[(size_t)(kc + k) * ldb + colBase + c];
        }
        __syncthreads();
#pragma unroll
        for (int k = 0; k < KC; k++) {
            float a[TM], b[TN];
#pragma unroll
            for (int i = 0; i < TM; i++) a[i] = As[k][ty * TM + i];
#pragma unroll
            for (int j = 0; j < TN; j++) b[j] = Bs[k][tx * TN + j];
#pragma unroll
            for (int i = 0; i < TM; i++)
#pragma unroll
                for (int j = 0; j < TN; j++) acc[i][j] += a[i] * b[j];
        }
        __syncthreads();
    }
#pragma unroll
    for (int i = 0; i < TM; i++) {
        int row = rowBase + ty * TM + i;
        if (row >= nrows) continue;
#pragma unroll
        for (int j = 0; j < TN; j++) {
            int col = colBase + tx * TN + j;
            C[(size_t)row * ldc + col] = fmaxf(acc[i][j] + bias[col], 0.0f);
        }
    }
}

__global__ void __launch_bounds__(256)
mlp2_kernel(const float* __restrict__ Wg2, const float* __restrict__ bias,
            float* __restrict__ out) {
    // mlp1(1024) @ Wg2 -> out [512,128], no relu
    constexpr int BM = 8, BN = 128, KC = 16, TM = 1, TN = 4, NT = 256;
    __shared__ __align__(16) float As[KC][BM];
    __shared__ __align__(16) float Bs[KC][BN];
    const float* A = g_mlp1; const float* B = Wg2; float* C = out;
    const int lda = 1024, ldb = 128, ldc = 128, nrows = N_GRAPHS, K = 1024;
    int tid = threadIdx.x;
    int tx = tid % (BN / TN), ty = tid / (BN / TN);
    int rowBase = blockIdx.y * BM, colBase = blockIdx.x * BN;
    float acc[TM][TN];
#pragma unroll
    for (int i = 0; i < TM; i++)
#pragma unroll
        for (int j = 0; j < TN; j++) acc[i][j] = 0.0f;
    for (int kc = 0; kc < K; kc += KC) {
        for (int e = tid; e < BM * KC; e += NT) {
            int r = e / KC, k = e % KC;
            int row = rowBase + r;
            As[k][r] = (row < nrows) ? A[(size_t)row * lda + kc + k] : 0.0f;
        }
#pragma unroll
        for (int e = tid * 4; e < KC * BN; e += NT * 4) {
            int k = e / BN, c = e % BN;
            *(float4*)&Bs[k][c] = *(const float4*)&B[(size_t)(kc + k) * ldb + colBase + c];
        }
        __syncthreads();
#pragma unroll
        for (int k = 0; k < KC; k++) {
            float a[TM], b[TN];
#pragma unroll
            for (int i = 0; i < TM; i++) a[i] = As[k][ty * TM + i];
#pragma unroll
            for (int j = 0; j < TN; j++) b[j] = Bs[k][tx * TN + j];
#pragma unroll
            for (int i = 0; i < TM; i++)
#pragma unroll
                for (int j = 0; j < TN; j++) acc[i][j] += a[i] * b[j];
        }
        __syncthreads();
    }
#pragma unroll
    for (int i = 0; i < TM; i++) {
        int row = rowBase + ty * TM + i;
        if (row >= nrows) continue;
#pragma unroll
        for (int j = 0; j < TN; j++) {
            int col = colBase + tx * TN + j;
            C[(size_t)row * ldc + col] = acc[i][j] + bias[col];
        }
    }
}

// ---------------- host ------------------------------------------------------
extern "C" void kernel_launch(void* const* d_in, const int* in_sizes, int n_in,
                              void* d_out, int out_size) {
    const float* x     = (const float*)d_in[0];
    const int*   ei    = (const int*)d_in[1];    // int32: JAX x64 disabled
    const int*   batch = (const int*)d_in[2];    // int32: JAX x64 disabled
    const float* W1    = (const float*)d_in[3];
    const float* b1    = (const float*)d_in[4];
    const float* W2    = (const float*)d_in[5];
    const float* b2    = (const float*)d_in[6];
    const float* Wg1   = (const float*)d_in[7];
    const float* bg1   = (const float*)d_in[8];
    const float* Wg2   = (const float*)d_in[9];
    const float* bg2   = (const float*)d_in[10];
    float*       out   = (float*)d_out;

    const int NB_SCAN = (N_NODES + 1023) / 1024;  // 98
    const int NB_ROWS = (N_NODES + 127) / 128;    // 782

    // degree histogram + CSR build
    zero_counts_kernel<<<(N_NODES + 255) / 256, 256>>>();
    hist_kernel<<<(N_EDGES + 255) / 256, 256>>>(ei);
    scan_chunks_kernel<<<NB_SCAN, 256>>>();
    scan_tops_kernel<<<1, 128>>>(NB_SCAN);
    scan_finalize_kernel<<<(N_NODES + 255) / 256, 256>>>();
    fill_kernel<<<(N_EDGES + 255) / 256, 256>>>(ei);
    pad_w1_kernel<<<(80 * 128 + 255) / 256, 256>>>(W1);

    // layer 1: aggregate x (78 feats -> 80 padded), then TF32 GEMM + bias + relu
    agg_x_kernel<<<N_NODES / 8, 256>>>(x);
    gemm1_tf32_kernel<<<dim3(1, NB_ROWS), 256>>>(b1);

    // layer 2: aggregate h1 (128 feats), then TF32 GEMM + bias + relu
    agg_h_kernel<<<N_NODES / 8, 256>>>();
    gemm2_tf32_kernel<<<dim3(2, NB_ROWS), 256>>>(W2, b2);

    // global max pool over sorted batch
    zero_pool_kernel<<<(N_GRAPHS * 256 + 255) / 256, 256>>>();
    seg_max_kernel<<<(N_NODES + 127) / 128, 256>>>(batch);

    // MLP head
    mlp1_kernel<<<dim3(8, 8), 256>>>(Wg1, bg1);
    mlp2_kernel<<<dim3(1, 64), 256>>>(Wg2, bg2, out);
}

// round 6
// speedup vs baseline: 1.3489x; 1.2204x over previous
#include <cuda_runtime.h>
#include <cstdint>

#define N_NODES  100000
#define N_EDGES  1600000
#define N_GRAPHS 512

// ---------------- scratch (device globals) ----------------------------------
__device__ int      g_counts[N_NODES];
__device__ int      g_rowstart[N_NODES + 1];
__device__ int      g_pos[N_NODES];
__device__ int      g_esrc[N_EDGES];
__device__ int      g_blocksums[128];
__device__ float    g_dinv[N_NODES];
__device__ uint32_t g_W1t[128 * 84];    // W1 transposed -> [n][k], tf32, k padded to 84
__device__ uint32_t g_W2t[256 * 132];   // W2 transposed -> [n][k], tf32, k padded to 132
__device__ float    g_h1[(size_t)N_NODES * 128];
__device__ float    g_pool[N_GRAPHS * 256];
__device__ float    g_mlp1[N_GRAPHS * 1024];

// ---------------- tf32 helpers ----------------------------------------------
__device__ __forceinline__ uint32_t f2tf32(float f) {
    uint32_t u;
    asm("cvt.rna.tf32.f32 %0, %1;" : "=r"(u) : "f"(f));
    return u;
}

__device__ __forceinline__ void mma_tf32(float* c, const uint32_t* a,
                                         uint32_t b0, uint32_t b1) {
    asm volatile(
        "mma.sync.aligned.m16n8k8.row.col.f32.tf32.tf32.f32 "
        "{%0,%1,%2,%3}, {%4,%5,%6,%7}, {%8,%9}, {%0,%1,%2,%3};"
        : "+f"(c[0]), "+f"(c[1]), "+f"(c[2]), "+f"(c[3])
        : "r"(a[0]), "r"(a[1]), "r"(a[2]), "r"(a[3]), "r"(b0), "r"(b1));
}

// ---------------- CSR build --------------------------------------------------
__global__ void zero_counts_kernel() {
    int i = blockIdx.x * blockDim.x + threadIdx.x;
    if (i < N_NODES) g_counts[i] = 0;
}

__global__ void zero_pool_kernel() {
    int i = blockIdx.x * blockDim.x + threadIdx.x;
    if (i < N_GRAPHS * 256) g_pool[i] = 0.0f;
}

__global__ void hist_kernel(const int* __restrict__ ei) {
    int e = blockIdx.x * blockDim.x + threadIdx.x;
    if (e < N_EDGES) {
        int d = ei[N_EDGES + e];
        if (d >= 0 && d < N_NODES) atomicAdd(&g_counts[d], 1);
    }
}

__device__ __forceinline__ int warp_incl_scan(int x) {
    int lane = threadIdx.x & 31;
#pragma unroll
    for (int o = 1; o < 32; o <<= 1) {
        int y = __shfl_up_sync(0xffffffffu, x, o);
        if (lane >= o) x += y;
    }
    return x;
}

__global__ void scan_chunks_kernel() {
    int base = blockIdx.x * 1024;
    int t = threadIdx.x;
    int i0 = base + t * 4;
    int v[4];
#pragma unroll
    for (int j = 0; j < 4; j++) v[j] = (i0 + j < N_NODES) ? g_counts[i0 + j] : 0;
    int s = v[0] + v[1] + v[2] + v[3];
    int incl = warp_incl_scan(s);
    __shared__ int ws[8];
    int lane = t & 31, wid = t >> 5;
    if (lane == 31) ws[wid] = incl;
    __syncthreads();
    if (wid == 0) {
        int w = (lane < 8) ? ws[lane] : 0;
        w = warp_incl_scan(w);
        if (lane < 8) ws[lane] = w;
    }
    __syncthreads();
    int excl = incl - s + (wid ? ws[wid - 1] : 0);
    int run = excl;
#pragma unroll
    for (int j = 0; j < 4; j++) {
        if (i0 + j < N_NODES) g_rowstart[i0 + j] = run;
        run += v[j];
    }
    if (t == 255) g_blocksums[blockIdx.x] = excl + s;
}

__global__ void scan_tops_kernel(int nb) {
    int t = threadIdx.x;
    int v = (t < nb) ? g_blocksums[t] : 0;
    int incl = warp_incl_scan(v);
    __shared__ int ws[4];
    int lane = t & 31, wid = t >> 5;
    if (lane == 31) ws[wid] = incl;
    __syncthreads();
    if (wid == 0) {
        int w = (lane < 4) ? ws[lane] : 0;
        w = warp_incl_scan(w);
        if (lane < 4) ws[lane] = w;
    }
    __syncthreads();
    int tot_incl = incl + (wid ? ws[wid - 1] : 0);
    if (t < nb) g_blocksums[t] = tot_incl - v;
}

__global__ void scan_finalize_kernel() {
    int i = blockIdx.x * blockDim.x + threadIdx.x;
    if (i < N_NODES) {
        int v = g_rowstart[i] + g_blocksums[i >> 10];
        g_rowstart[i] = v;
        g_pos[i] = v;
        g_dinv[i] = rsqrtf((float)g_counts[i] + 1.0f);
    }
    if (i == 0) g_rowstart[N_NODES] = N_EDGES;
}

__global__ void fill_kernel(const int* __restrict__ ei) {
    int e = blockIdx.x * blockDim.x + threadIdx.x;
    if (e < N_EDGES) {
        int d = ei[N_EDGES + e];
        int s = ei[e];
        if (d >= 0 && d < N_NODES) {
            int idx = atomicAdd(&g_pos[d], 1);
            if (idx >= 0 && idx < N_EDGES) g_esrc[idx] = s;
        }
    }
}

// ---------------- weight transpose + tf32 precompute -------------------------
__global__ void w1t_kernel(const float* __restrict__ W1) {  // W1 [78,128] -> W1t [128][84]
    int i = blockIdx.x * blockDim.x + threadIdx.x;
    if (i < 128 * 84) {
        int n = i / 84, k = i % 84;
        g_W1t[i] = (k < 78) ? f2tf32(W1[k * 128 + n]) : 0u;
    }
}

__global__ void w2t_kernel(const float* __restrict__ W2) {  // W2 [128,256] -> W2t [256][132]
    int i = blockIdx.x * blockDim.x + threadIdx.x;
    if (i < 256 * 132) {
        int n = i / 132, k = i % 132;
        g_W2t[i] = (k < 128) ? f2tf32(W2[k * 256 + n]) : 0u;
    }
}

// ---------------- fused layer 1: agg_x + TF32 GEMM + bias + relu -> h1 -------
// block = 128 nodes, 512 threads (16 warps). SMEM: As[128][84] + Bs[128][84] u32.
__global__ void __launch_bounds__(512)
fused1_kernel(const float* __restrict__ x, const float* __restrict__ bias) {
    extern __shared__ uint32_t sm1[];
    uint32_t* As = sm1;                 // 128*84
    uint32_t* Bs = sm1 + 128 * 84;      // 128*84
    int tid = threadIdx.x, wid = tid >> 5, lane = tid & 31;
    int tileBase = blockIdx.x * 128;

    // stage W1t -> Bs (coalesced uint4 row copies; only k<80 needed)
    for (int idx = tid; idx < 128 * 20; idx += 512) {
        int n = idx / 20, q = idx % 20;
        ((uint4*)(Bs + n * 84))[q] = ((const uint4*)(g_W1t + n * 84))[q];
    }

    // aggregation: warp per node, 8 nodes per warp
    for (int r = 0; r < 8; r++) {
        int row = wid + r * 16;
        int i = tileBase + row;
        if (i < N_NODES) {
            float di = g_dinv[i];
            int beg = g_rowstart[i], end = g_rowstart[i + 1];
            float a0 = 0.f, a1 = 0.f, a2 = 0.f;
            for (int e = beg; e < end; e++) {
                int s = g_esrc[e];
                float w = g_dinv[s] * di;
                const float* xs = x + (size_t)s * 78;
                a0 += xs[lane] * w;
                a1 += xs[lane + 32] * w;
                if (lane < 14) a2 += xs[lane + 64] * w;
            }
            float sd = di * di;
            const float* xi = x + (size_t)i * 78;
            a0 += xi[lane] * sd;
            a1 += xi[lane + 32] * sd;
            if (lane < 14) a2 += xi[lane + 64] * sd;
            As[row * 84 + lane] = f2tf32(a0);
            As[row * 84 + lane + 32] = f2tf32(a1);
            if (lane < 16) As[row * 84 + lane + 64] = (lane < 14) ? f2tf32(a2) : 0u;
        } else {
            As[row * 84 + lane] = 0u;
            As[row * 84 + lane + 32] = 0u;
            if (lane < 16) As[row * 84 + lane + 64] = 0u;
        }
    }
    __syncthreads();

    // MMA: 16 warps, warp tile 32 rows x 32 cols
    int lq = lane >> 2, lr = lane & 3;
    int warpRow = wid & 3, warpCol = wid >> 2;  // 0..3, 0..3
    float c[2][4][4] = {};
#pragma unroll
    for (int ks = 0; ks < 10; ks++) {
        uint32_t a[2][4];
#pragma unroll
        for (int am = 0; am < 2; am++) {
            int rr = warpRow * 32 + am * 16 + lq;
            a[am][0] = As[rr * 84 + ks * 8 + lr];
            a[am][1] = As[(rr + 8) * 84 + ks * 8 + lr];
            a[am][2] = As[rr * 84 + ks * 8 + lr + 4];
            a[am][3] = As[(rr + 8) * 84 + ks * 8 + lr + 4];
        }
#pragma unroll
        for (int an = 0; an < 4; an++) {
            int n = warpCol * 32 + an * 8 + lq;
            uint32_t b0 = Bs[n * 84 + ks * 8 + lr];
            uint32_t b1 = Bs[n * 84 + ks * 8 + lr + 4];
            mma_tf32(c[0][an], a[0], b0, b1);
            mma_tf32(c[1][an], a[1], b0, b1);
        }
    }

    // epilogue -> h1 (bias + relu)
#pragma unroll
    for (int am = 0; am < 2; am++) {
        int r0 = tileBase + warpRow * 32 + am * 16 + lq;
#pragma unroll
        for (int an = 0; an < 4; an++) {
            int col = warpCol * 32 + an * 8 + lr * 2;
            float bx = bias[col], by = bias[col + 1];
            float v0 = fmaxf(c[am][an][0] + bx, 0.f);
            float v1 = fmaxf(c[am][an][1] + by, 0.f);
            float v2 = fmaxf(c[am][an][2] + bx, 0.f);
            float v3 = fmaxf(c[am][an][3] + by, 0.f);
            if (r0 < N_NODES)
                *(float2*)&g_h1[(size_t)r0 * 128 + col] = make_float2(v0, v1);
            if (r0 + 8 < N_NODES)
                *(float2*)&g_h1[(size_t)(r0 + 8) * 128 + col] = make_float2(v2, v3);
        }
    }
}

// ---------------- fused layer 2: agg_h + TF32 GEMM + bias + relu + seg-max ---
// block = 128 nodes, 512 threads. SMEM: As[128][132] + Bs[256][36] u32.
// Epilogue: atomicMax into pool (h2 never materialized). batch is sorted.
__global__ void __launch_bounds__(512)
fused2_kernel(const float* __restrict__ bias, const int* __restrict__ batch) {
    extern __shared__ uint32_t sm2[];
    uint32_t* As = sm2;                  // 128*132
    uint32_t* Bs = sm2 + 128 * 132;      // 256*36
    int tid = threadIdx.x, wid = tid >> 5, lane = tid & 31;
    int tileBase = blockIdx.x * 128;

    // aggregation: warp per node over h1 [N,128]
    for (int r = 0; r < 8; r++) {
        int row = wid + r * 16;
        int i = tileBase + row;
        uint4 t = make_uint4(0u, 0u, 0u, 0u);
        if (i < N_NODES) {
            float di = g_dinv[i];
            int beg = g_rowstart[i], end = g_rowstart[i + 1];
            float4 acc = make_float4(0.f, 0.f, 0.f, 0.f);
            for (int e = beg; e < end; e++) {
                int s = g_esrc[e];
                float w = g_dinv[s] * di;
                float4 v = ((const float4*)(g_h1 + (size_t)s * 128))[lane];
                acc.x += v.x * w; acc.y += v.y * w;
                acc.z += v.z * w; acc.w += v.w * w;
            }
            float sd = di * di;
            float4 v = ((const float4*)(g_h1 + (size_t)i * 128))[lane];
            acc.x += v.x * sd; acc.y += v.y * sd;
            acc.z += v.z * sd; acc.w += v.w * sd;
            t = make_uint4(f2tf32(acc.x), f2tf32(acc.y), f2tf32(acc.z), f2tf32(acc.w));
        }
        ((uint4*)(As + row * 132))[lane] = t;
    }
    __syncthreads();

    // MMA: 16 warps, warp tile 32 rows x 64 cols; K chunked by 32
    int lq = lane >> 2, lr = lane & 3;
    int warpRow = wid & 3, warpCol = wid >> 2;  // 0..3, 0..3
    float c[2][8][4] = {};
    for (int kc = 0; kc < 128; kc += 32) {
        // stage W2t chunk -> Bs[n][0..31] (stride 36)
        for (int idx = tid; idx < 2048; idx += 512) {
            int n = idx / 8, q = idx % 8;
            ((uint4*)(Bs + n * 36))[q] = ((const uint4*)(g_W2t + n * 132 + kc))[q];
        }
        __syncthreads();
#pragma unroll
        for (int ks = 0; ks < 4; ks++) {
            uint32_t a[2][4];
#pragma unroll
            for (int am = 0; am < 2; am++) {
                int rr = warpRow * 32 + am * 16 + lq;
                a[am][0] = As[rr * 132 + kc + ks * 8 + lr];
                a[am][1] = As[(rr + 8) * 132 + kc + ks * 8 + lr];
                a[am][2] = As[rr * 132 + kc + ks * 8 + lr + 4];
                a[am][3] = As[(rr + 8) * 132 + kc + ks * 8 + lr + 4];
            }
#pragma unroll
            for (int an = 0; an < 8; an++) {
                int n = warpCol * 64 + an * 8 + lq;
                uint32_t b0 = Bs[n * 36 + ks * 8 + lr];
                uint32_t b1 = Bs[n * 36 + ks * 8 + lr + 4];
                mma_tf32(c[0][an], a[0], b0, b1);
                mma_tf32(c[1][an], a[1], b0, b1);
            }
        }
        __syncthreads();
    }

    // epilogue: bias + relu, then segment max straight into pool via atomicMax.
#pragma unroll
    for (int am = 0; am < 2; am++) {
        int r0 = tileBase + warpRow * 32 + am * 16 + lq;
        int r1 = r0 + 8;
        int b_lo = (r0 < N_NODES) ? batch[r0] : -1;
        int b_hi = (r1 < N_NODES) ? batch[r1] : -1;
        if (b_lo >= N_GRAPHS) b_lo = -1;
        if (b_hi >= N_GRAPHS) b_hi = -1;
#pragma unroll
        for (int an = 0; an < 8; an++) {
            int col = warpCol * 64 + an * 8 + lr * 2;
            float bx = bias[col], by = bias[col + 1];
            float v0 = fmaxf(c[am][an][0] + bx, 0.f);
            float v1 = fmaxf(c[am][an][1] + by, 0.f);
            float v2 = fmaxf(c[am][an][2] + bx, 0.f);
            float v3 = fmaxf(c[am][an][3] + by, 0.f);
            if (b_lo == b_hi && b_lo >= 0) {
                atomicMax((int*)&g_pool[(size_t)b_lo * 256 + col],
                          __float_as_int(fmaxf(v0, v2)));
                atomicMax((int*)&g_pool[(size_t)b_lo * 256 + col + 1],
                          __float_as_int(fmaxf(v1, v3)));
            } else {
                if (b_lo >= 0) {
                    atomicMax((int*)&g_pool[(size_t)b_lo * 256 + col], __float_as_int(v0));
                    atomicMax((int*)&g_pool[(size_t)b_lo * 256 + col + 1], __float_as_int(v1));
                }
                if (b_hi >= 0) {
                    atomicMax((int*)&g_pool[(size_t)b_hi * 256 + col], __float_as_int(v2));
                    atomicMax((int*)&g_pool[(size_t)b_hi * 256 + col + 1], __float_as_int(v3));
                }
            }
        }
    }
}

// ---------------- fp32 MLP head (small) -------------------------------------
__global__ void __launch_bounds__(256)
mlp1_kernel(const float* __restrict__ Wg1, const float* __restrict__ bias) {
    constexpr int BM = 64, BN = 128, KC = 16, TM = 8, TN = 4, NT = 256;
    __shared__ __align__(16) float As[KC][BM];
    __shared__ __align__(16) float Bs[KC][BN];
    const float* A = g_pool; const float* B = Wg1; float* C = g_mlp1;
    const int lda = 256, ldb = 1024, ldc = 1024, nrows = N_GRAPHS, K = 256;
    int tid = threadIdx.x;
    int tx = tid % (BN / TN), ty = tid / (BN / TN);
    int rowBase = blockIdx.y * BM, colBase = blockIdx.x * BN;
    float acc[TM][TN];
#pragma unroll
    for (int i = 0; i < TM; i++)
#pragma unroll
        for (int j = 0; j < TN; j++) acc[i][j] = 0.0f;
    for (int kc = 0; kc < K; kc += KC) {
#pragma unroll
        for (int e = tid * 4; e < BM * KC; e += NT * 4) {
            int r = e / KC, k = e % KC;
            int row = rowBase + r;
            float4 v = (row < nrows) ? *(const float4*)&A[(size_t)row * lda + kc + k]
                                     : make_float4(0.f, 0.f, 0.f, 0.f);
            As[k][r] = v.x; As[k + 1][r] = v.y; As[k + 2][r] = v.z; As[k + 3][r] = v.w;
        }
#pragma unroll
        for (int e = tid * 4; e < KC * BN; e += NT * 4) {
            int k = e / BN, c = e % BN;
            *(float4*)&Bs[k][c] = *(const float4*)&B[(size_t)(kc + k) * ldb + colBase + c];
        }
        __syncthreads();
#pragma unroll
        for (int k = 0; k < KC; k++) {
            float a[TM], b[TN];
#pragma unroll
            for (int i = 0; i < TM; i++) a[i] = As[k][ty * TM + i];
#pragma unroll
            for (int j = 0; j < TN; j++) b[j] = Bs[k][tx * TN + j];
#pragma unroll
            for (int i = 0; i < TM; i++)
#pragma unroll
                for (int j = 0; j < TN; j++) acc[i][j] += a[i] * b[j];
        }
        __syncthreads();
    }
#pragma unroll
    for (int i = 0; i < TM; i++) {
        int row = rowBase + ty * TM + i;
        if (row >= nrows) continue;
#pragma unroll
        for (int j = 0; j < TN; j++) {
            int col = colBase + tx * TN + j;
            C[(size_t)row * ldc + col] = fmaxf(acc[i][j] + bias[col], 0.0f);
        }
    }
}

__global__ void __launch_bounds__(256)
mlp2_kernel(const float* __restrict__ Wg2, const float* __restrict__ bias,
            float* __restrict__ out) {
    constexpr int BM = 8, BN = 128, KC = 16, TM = 1, TN = 4, NT = 256;
    __shared__ __align__(16) float As[KC][BM];
    __shared__ __align__(16) float Bs[KC][BN];
    const float* A = g_mlp1; const float* B = Wg2; float* C = out;
    const int lda = 1024, ldb = 128, ldc = 128, nrows = N_GRAPHS, K = 1024;
    int tid = threadIdx.x;
    int tx = tid % (BN / TN), ty = tid / (BN / TN);
    int rowBase = blockIdx.y * BM, colBase = blockIdx.x * BN;
    float acc[TM][TN];
#pragma unroll
    for (int i = 0; i < TM; i++)
#pragma unroll
        for (int j = 0; j < TN; j++) acc[i][j] = 0.0f;
    for (int kc = 0; kc < K; kc += KC) {
        for (int e = tid; e < BM * KC; e += NT) {
            int r = e / KC, k = e % KC;
            int row = rowBase + r;
            As[k][r] = (row < nrows) ? A[(size_t)row * lda + kc + k] : 0.0f;
        }
#pragma unroll
        for (int e = tid * 4; e < KC * BN; e += NT * 4) {
            int k = e / BN, c = e % BN;
            *(float4*)&Bs[k][c] = *(const float4*)&B[(size_t)(kc + k) * ldb + colBase + c];
        }
        __syncthreads();
#pragma unroll
        for (int k = 0; k < KC; k++) {
            float a[TM], b[TN];
#pragma unroll
            for (int i = 0; i < TM; i++) a[i] = As[k][ty * TM + i];
#pragma unroll
            for (int j = 0; j < TN; j++) b[j] = Bs[k][tx * TN + j];
#pragma unroll
            for (int i = 0; i < TM; i++)
#pragma unroll
                for (int j = 0; j < TN; j++) acc[i][j] += a[i] * b[j];
        }
        __syncthreads();
    }
#pragma unroll
    for (int i = 0; i < TM; i++) {
        int row = rowBase + ty * TM + i;
        if (row >= nrows) continue;
#pragma unroll
        for (int j = 0; j < TN; j++) {
            int col = colBase + tx * TN + j;
            C[(size_t)row * ldc + col] = acc[i][j] + bias[col];
        }
    }
}

// ---------------- host ------------------------------------------------------
extern "C" void kernel_launch(void* const* d_in, const int* in_sizes, int n_in,
                              void* d_out, int out_size) {
    const float* x     = (const float*)d_in[0];
    const int*   ei    = (const int*)d_in[1];    // int32 (JAX x64 disabled)
    const int*   batch = (const int*)d_in[2];    // int32
    const float* W1    = (const float*)d_in[3];
    const float* b1    = (const float*)d_in[4];
    const float* W2    = (const float*)d_in[5];
    const float* b2    = (const float*)d_in[6];
    const float* Wg1   = (const float*)d_in[7];
    const float* bg1   = (const float*)d_in[8];
    const float* Wg2   = (const float*)d_in[9];
    const float* bg2   = (const float*)d_in[10];
    float*       out   = (float*)d_out;

    const int SMEM1 = 128 * 84 * 2 * 4;               // 86016 B
    const int SMEM2 = (128 * 132 + 256 * 36) * 4;     // 104448 B
    cudaFuncSetAttribute(fused1_kernel, cudaFuncAttributeMaxDynamicSharedMemorySize, SMEM1);
    cudaFuncSetAttribute(fused2_kernel, cudaFuncAttributeMaxDynamicSharedMemorySize, SMEM2);

    const int NB_SCAN = (N_NODES + 1023) / 1024;  // 98
    const int NB_ROWS = (N_NODES + 127) / 128;    // 782

    // CSR build + weight prep + pool init
    zero_counts_kernel<<<(N_NODES + 255) / 256, 256>>>();
    hist_kernel<<<(N_EDGES + 255) / 256, 256>>>(ei);
    scan_chunks_kernel<<<NB_SCAN, 256>>>();
    scan_tops_kernel<<<1, 128>>>(NB_SCAN);
    scan_finalize_kernel<<<(N_NODES + 255) / 256, 256>>>();
    fill_kernel<<<(N_EDGES + 255) / 256, 256>>>(ei);
    w1t_kernel<<<(128 * 84 + 255) / 256, 256>>>(W1);
    w2t_kernel<<<(256 * 132 + 255) / 256, 256>>>(W2);
    zero_pool_kernel<<<(N_GRAPHS * 256 + 255) / 256, 256>>>();

    // fused layers
    fused1_kernel<<<NB_ROWS, 512, SMEM1>>>(x, b1);
    fused2_kernel<<<NB_ROWS, 512, SMEM2>>>(b2, batch);

    // MLP head
    mlp1_kernel<<<dim3(8, 8), 256>>>(Wg1, bg1);
    mlp2_kernel<<<dim3(1, 64), 256>>>(Wg2, bg2, out);
}